// round 16
// baseline (speedup 1.0000x reference)
#include <cuda_runtime.h>
#include <cuda_fp16.h>
#include <cstdint>

#define NN 50000
#define EE 800000
#define DD 64
#define NB 196    // (NN + 255) / 256 scan blocks
#define PH 136    // sI/sW row pitch in halfs (272B: ldmatrix bank-conflict-free)
#define IDXCAP 1600

// Scratch (device globals — allocation-free per harness rules)
__device__ __align__(16) __half2 g_xh[NN * DD / 2]; // x as fp16 (gather + self)
__device__ __align__(16) __half2 g_hh[NN * DD / 2]; // h as fp16 (gather + self)
__device__ int g_src32[EE];
__device__ int g_dst32[EE];
__device__ int g_deg[NN];
__device__ int g_loc[NN];
__device__ int g_bsum[NB];
__device__ int g_bbase[NB];
__device__ int g_csr_src[EE];
__device__ int g_scan_count;

__device__ __forceinline__ int node_off(int n) {
    return g_loc[n] + g_bbase[n >> 8];
}

// ---------------------------------------------------------------------------
// Kernel 0: convert x -> fp16 (grid-stride)
// ---------------------------------------------------------------------------
__global__ __launch_bounds__(256) void tohalf_kernel(const float* __restrict__ x) {
    int stride = gridDim.x * 256;
    for (int i = blockIdx.x * 256 + threadIdx.x; i < NN * DD / 2; i += stride) {
        float2 v = reinterpret_cast<const float2*>(x)[i];
        g_xh[i] = __floats2half2_rn(v.x, v.y);
    }
}

// ---------------------------------------------------------------------------
// Kernel 1: normalize indices to int32 + degree histogram (R14 shape:
// 1 edge/thread, 3125 blocks). Dtype self-detect per block.
// ---------------------------------------------------------------------------
__global__ __launch_bounds__(256) void convert_kernel(const void* __restrict__ ei) {
    const int* ei32 = (const int*)ei;
    __shared__ int s_is64;
    if (threadIdx.x == 0) s_is64 = 1;
    __syncthreads();
    if (threadIdx.x < 64 && ei32[2 * threadIdx.x + 1] != 0) atomicExch(&s_is64, 0);
    __syncthreads();

    int e = blockIdx.x * blockDim.x + threadIdx.x;
    if (e >= EE) return;
    int s, d;
    if (s_is64) {
        const long long* p = (const long long*)ei;
        s = (int)p[e];
        d = (int)p[EE + e];
    } else {
        const int* p = (const int*)ei;
        s = p[e];
        d = p[EE + e];
    }
    s = min(max(s, 0), NN - 1);
    d = min(max(d, 0), NN - 1);
    g_src32[e] = s;
    g_dst32[e] = d;
    atomicAdd(&g_deg[d], 1);
}

// ---------------------------------------------------------------------------
// Kernel 2: single-pass exclusive scan (decoupled last-block)
// ---------------------------------------------------------------------------
__global__ __launch_bounds__(256) void scan_kernel() {
    __shared__ int sh[256];
    __shared__ int is_last;
    int tid = threadIdx.x;
    int i = blockIdx.x * 256 + tid;
    int v = (i < NN) ? g_deg[i] : 0;
    sh[tid] = v;
    __syncthreads();
    #pragma unroll
    for (int d = 1; d < 256; d <<= 1) {
        int t = (tid >= d) ? sh[tid - d] : 0;
        __syncthreads();
        sh[tid] += t;
        __syncthreads();
    }
    if (i < NN) g_loc[i] = sh[tid] - v;
    if (tid == 255) g_bsum[blockIdx.x] = sh[255];

    __threadfence();
    if (tid == 0) is_last = (atomicAdd(&g_scan_count, 1) == NB - 1);
    __syncthreads();

    if (is_last) {
        int v2 = (tid < NB) ? g_bsum[tid] : 0;
        sh[tid] = v2;
        __syncthreads();
        #pragma unroll
        for (int d = 1; d < 256; d <<= 1) {
            int t = (tid >= d) ? sh[tid - d] : 0;
            __syncthreads();
            sh[tid] += t;
            __syncthreads();
        }
        if (tid < NB) g_bbase[tid] = sh[tid] - v2;
        if (tid == 0) g_scan_count = 0;
    }
}

// ---------------------------------------------------------------------------
// Kernel 3: CSR fill (R14 shape: 1 edge/thread). g_deg drains to 0.
// ---------------------------------------------------------------------------
__global__ __launch_bounds__(256) void fill_kernel() {
    int e = blockIdx.x * blockDim.x + threadIdx.x;
    if (e >= EE) return;
    int d = g_dst32[e];
    int off = node_off(d);
    int slot = atomicSub(&g_deg[d], 1) - 1;
    g_csr_src[off + slot] = g_src32[e];
}

// ---------------------------------------------------------------------------
// ldmatrix / mma helpers
// ---------------------------------------------------------------------------
__device__ __forceinline__ void ldsm_x4(uint32_t addr, uint32_t& a0, uint32_t& a1,
                                        uint32_t& a2, uint32_t& a3) {
    asm volatile("ldmatrix.sync.aligned.m8n8.x4.shared.b16 {%0,%1,%2,%3}, [%4];"
                 : "=r"(a0), "=r"(a1), "=r"(a2), "=r"(a3) : "r"(addr));
}
__device__ __forceinline__ void ldsm_x2(uint32_t addr, uint32_t& b0, uint32_t& b1) {
    asm volatile("ldmatrix.sync.aligned.m8n8.x2.shared.b16 {%0,%1}, [%2];"
                 : "=r"(b0), "=r"(b1) : "r"(addr));
}
__device__ __forceinline__ void mma16816(float* c, uint32_t a0, uint32_t a1,
                                         uint32_t a2, uint32_t a3,
                                         uint32_t b0, uint32_t b1) {
    asm volatile(
        "mma.sync.aligned.m16n8k16.row.col.f32.f16.f16.f32 "
        "{%0,%1,%2,%3}, {%4,%5,%6,%7}, {%8,%9}, {%0,%1,%2,%3};"
        : "+f"(c[0]), "+f"(c[1]), "+f"(c[2]), "+f"(c[3])
        : "r"(a0), "r"(a1), "r"(a2), "r"(a3), "r"(b0), "r"(b1));
}

#define ACCH(a, u) {                                            \
    __half2 _h0 = *reinterpret_cast<const __half2*>(&(u).x);    \
    __half2 _h1 = *reinterpret_cast<const __half2*>(&(u).y);    \
    float2 _f0 = __half22float2(_h0);                           \
    float2 _f1 = __half22float2(_h1);                           \
    (a).x += _f0.x; (a).y += _f0.y; (a).z += _f1.x; (a).w += _f1.y; }

// ---------------------------------------------------------------------------
// Kernel 4/5: FUSED aggregation + tensor-core MLP.
// New in R16: (a) block's contiguous CSR index range staged coalesced into
// sIdx (LDS replaces the dependent scattered index LDG); (b) half-warps
// work-steal node PAIRS off a shared counter (kills degree-sum stragglers).
// Compute phase unchanged from the R14 win.
// ---------------------------------------------------------------------------
template <int LAYER>
__global__ __launch_bounds__(256) void fused_kernel(
    const float* __restrict__ Wl,
    const float* __restrict__ bl,
    const float* __restrict__ Wr,
    float* __restrict__ outext)
{
    const __half2* nb = (LAYER == 1) ? g_xh : g_hh;   // fp16 rows (neighbors+self)

    __shared__ __half sI[64 * PH];
    __shared__ __half sW[64 * PH];
    __shared__ float  sB[DD];
    __shared__ int    sIdx[IDXCAP];
    __shared__ int    sCnt;

    const int base = blockIdx.x << 6;       // base < NN for all 782 blocks

    // Block's CSR range (contiguous): stage indices coalesced
    const int E0 = node_off(base);
    const int E1 = (base + 64 < NN) ? node_off(base + 64) : EE;
    const int Lc = min(E1 - E0, IDXCAP);
    for (int t = threadIdx.x; t < Lc; t += 256) sIdx[t] = g_csr_src[E0 + t];

    // Stage combined weights [j][k0..127] as fp16
    for (int t = threadIdx.x; t < 64 * 128; t += 256) {
        int j = t >> 7, kk = t & 127;
        float v = (kk < 64) ? Wl[(j << 6) + kk] : Wr[(j << 6) + kk - 64];
        sW[j * PH + kk] = __float2half_rn(v);
    }
    if (threadIdx.x < DD) sB[threadIdx.x] = bl[threadIdx.x];
    if (threadIdx.x == 0) sCnt = 0;
    __syncthreads();

    const int lane = threadIdx.x & 31;
    const int fl   = lane & 15;             // feature float4 index
    const int fo   = fl << 2;

    // ---- Gather + stage: half-warps steal node pairs (32 pairs total) ----
    while (true) {
        int pr = 0;
        if ((lane & 15) == 0) pr = atomicAdd(&sCnt, 1);
        pr = __shfl_sync(0xFFFFFFFFu, pr, 0, 16);   // broadcast within half-warp
        if (pr >= 32) break;

        int nodeA = pr << 1;
        int nodeB = nodeA + 1;
        int niA = base + nodeA;
        int niB = base + nodeB;
        int begA = 0, lenA = 0, begB = 0, lenB = 0;
        if (niA < NN) {
            begA = node_off(niA);
            lenA = ((niA + 1 < NN) ? node_off(niA + 1) : EE) - begA;
        }
        if (niB < NN) {
            begB = node_off(niB);
            lenB = ((niB + 1 < NN) ? node_off(niB + 1) : EE) - begB;
        }
        int relA = begA - E0;
        int relB = begB - E0;

        float4 aA0 = make_float4(0.f, 0.f, 0.f, 0.f);
        float4 aA1 = make_float4(0.f, 0.f, 0.f, 0.f);
        float4 aB0 = make_float4(0.f, 0.f, 0.f, 0.f);
        float4 aB1 = make_float4(0.f, 0.f, 0.f, 0.f);

        int m = max(lenA, lenB);
        #pragma unroll 1
        for (int i = 0; i < m; i += 2) {
            int sA0 = -1, sA1 = -1, sB0 = -1, sB1 = -1;
            if (i < lenA)
                sA0 = (relA + i < Lc) ? sIdx[relA + i] : g_csr_src[begA + i];
            if (i + 1 < lenA)
                sA1 = (relA + i + 1 < Lc) ? sIdx[relA + i + 1] : g_csr_src[begA + i + 1];
            if (i < lenB)
                sB0 = (relB + i < Lc) ? sIdx[relB + i] : g_csr_src[begB + i];
            if (i + 1 < lenB)
                sB1 = (relB + i + 1 < Lc) ? sIdx[relB + i + 1] : g_csr_src[begB + i + 1];
            if (sA0 >= 0) { uint2 u = reinterpret_cast<const uint2*>(nb + (size_t)sA0 * 32)[fl]; ACCH(aA0, u); }
            if (sA1 >= 0) { uint2 u = reinterpret_cast<const uint2*>(nb + (size_t)sA1 * 32)[fl]; ACCH(aA1, u); }
            if (sB0 >= 0) { uint2 u = reinterpret_cast<const uint2*>(nb + (size_t)sB0 * 32)[fl]; ACCH(aB0, u); }
            if (sB1 >= 0) { uint2 u = reinterpret_cast<const uint2*>(nb + (size_t)sB1 * 32)[fl]; ACCH(aB1, u); }
        }

        float invA = 1.0f / (float)max(lenA, 1);
        float invB = 1.0f / (float)max(lenB, 1);
        {
            __half2 p0 = __floats2half2_rn((aA0.x + aA1.x) * invA, (aA0.y + aA1.y) * invA);
            __half2 p1 = __floats2half2_rn((aA0.z + aA1.z) * invA, (aA0.w + aA1.w) * invA);
            uint2 u; u.x = *reinterpret_cast<uint32_t*>(&p0); u.y = *reinterpret_cast<uint32_t*>(&p1);
            *reinterpret_cast<uint2*>(&sI[nodeA * PH + fo]) = u;
        }
        {
            __half2 p0 = __floats2half2_rn((aB0.x + aB1.x) * invB, (aB0.y + aB1.y) * invB);
            __half2 p1 = __floats2half2_rn((aB0.z + aB1.z) * invB, (aB0.w + aB1.w) * invB);
            uint2 u; u.x = *reinterpret_cast<uint32_t*>(&p0); u.y = *reinterpret_cast<uint32_t*>(&p1);
            *reinterpret_cast<uint2*>(&sI[nodeB * PH + fo]) = u;
        }

        uint2 uA = make_uint2(0u, 0u), uB = make_uint2(0u, 0u);
        if (niA < NN) uA = reinterpret_cast<const uint2*>(nb + (size_t)niA * 32)[fl];
        if (niB < NN) uB = reinterpret_cast<const uint2*>(nb + (size_t)niB * 32)[fl];
        *reinterpret_cast<uint2*>(&sI[nodeA * PH + DD + fo]) = uA;
        *reinterpret_cast<uint2*>(&sI[nodeB * PH + DD + fo]) = uB;
    }
    __syncthreads();

    // ---- Compute: tensor cores. Warp tile: 16 nodes x 32 j ----
    const int wid = threadIdx.x >> 5;
    const int mw = (wid & 3) << 4;
    const int jw = (wid >> 2) << 5;

    float c[4][4];
    #pragma unroll
    for (int js = 0; js < 4; js++)
        #pragma unroll
        for (int q = 0; q < 4; q++) c[js][q] = 0.f;

    uint32_t siBase = (uint32_t)__cvta_generic_to_shared(sI);
    uint32_t swBase = (uint32_t)__cvta_generic_to_shared(sW);
    const int rA = lane & 15, cbA = lane >> 4;
    const int rB = lane & 7,  kbB = (lane >> 3) & 1;

    #pragma unroll
    for (int ks = 0; ks < 8; ks++) {
        int k0 = ks << 4;
        uint32_t a0, a1, a2, a3;
        ldsm_x4(siBase + (uint32_t)(((mw + rA) * PH + k0 + cbA * 8) * 2), a0, a1, a2, a3);
        #pragma unroll
        for (int js = 0; js < 4; js++) {
            uint32_t b0, b1;
            ldsm_x2(swBase + (uint32_t)(((jw + (js << 3) + rB) * PH + k0 + kbB * 8) * 2), b0, b1);
            mma16816(c[js], a0, a1, a2, a3, b0, b1);
        }
    }

    // ---- Epilogue ----
    const int r1 = mw + (lane >> 2);
    const int r2 = r1 + 8;
    const int cc = (lane & 3) << 1;
    const int ni1 = base + r1;
    const int ni2 = base + r2;

    #pragma unroll
    for (int js = 0; js < 4; js++) {
        int j = jw + (js << 3) + cc;
        float bx = sB[j], by = sB[j + 1];
        float v0 = c[js][0] + bx, v1 = c[js][1] + by;
        float v2 = c[js][2] + bx, v3 = c[js][3] + by;
        if (LAYER == 1) {
            v0 = tanhf(v0); v1 = tanhf(v1);
            v2 = tanhf(v2); v3 = tanhf(v3);
            if (ni1 < NN) g_hh[(size_t)ni1 * 32 + (j >> 1)] = __floats2half2_rn(v0, v1);
            if (ni2 < NN) g_hh[(size_t)ni2 * 32 + (j >> 1)] = __floats2half2_rn(v2, v3);
        } else {
            if (ni1 < NN) *reinterpret_cast<float2*>(outext + (size_t)ni1 * DD + j) = make_float2(v0, v1);
            if (ni2 < NN) *reinterpret_cast<float2*>(outext + (size_t)ni2 * DD + j) = make_float2(v2, v3);
        }
    }
}

// ---------------------------------------------------------------------------
// Launch
// ---------------------------------------------------------------------------
extern "C" void kernel_launch(void* const* d_in, const int* in_sizes, int n_in,
                              void* d_out, int out_size)
{
    const float* x    = (const float*)d_in[0];
    const void*  ei   = d_in[1];
    const float* Wl1  = (const float*)d_in[2];
    const float* bl1  = (const float*)d_in[3];
    const float* Wr1  = (const float*)d_in[4];
    const float* Wl2  = (const float*)d_in[5];
    const float* bl2  = (const float*)d_in[6];
    const float* Wr2  = (const float*)d_in[7];
    float*       out  = (float*)d_out;

    static void* deg_addr = nullptr;
    if (!deg_addr) cudaGetSymbolAddress(&deg_addr, g_deg);

    const int eb = (EE + 255) / 256;        // 1 edge/thread blocks
    const int fb = (NN + 63) / 64;          // 782 fused blocks

    cudaMemsetAsync(deg_addr, 0, NN * sizeof(int));
    tohalf_kernel<<<592, 256>>>(x);
    convert_kernel<<<eb, 256>>>(ei);
    scan_kernel<<<NB, 256>>>();
    fill_kernel<<<eb, 256>>>();
    fused_kernel<1><<<fb, 256>>>(Wl1, bl1, Wr1, nullptr);
    fused_kernel<2><<<fb, 256>>>(Wl2, bl2, Wr2, out);
}

// round 17
// speedup vs baseline: 1.2604x; 1.2604x over previous
#include <cuda_runtime.h>
#include <cuda_fp16.h>
#include <cstdint>

#define NN 50000
#define EE 800000
#define DD 64
#define NB 196    // (NN + 255) / 256 scan blocks
#define PH 136    // sI/sW row pitch in halfs (272B: ldmatrix bank-conflict-free)

// Scratch (device globals — allocation-free per harness rules)
__device__ __align__(16) __half2 g_xh[NN * DD / 2]; // x as fp16 (gather + self)
__device__ __align__(16) __half2 g_hh[NN * DD / 2]; // h as fp16 (gather + self)
__device__ int g_src32[EE];
__device__ int g_dst32[EE];
__device__ int g_deg[NN];
__device__ int g_loc[NN];
__device__ int g_bsum[NB];
__device__ int g_bbase[NB];
__device__ int g_csr_src[EE];
__device__ int g_scan_count;

__device__ __forceinline__ int node_off(int n) {
    return g_loc[n] + g_bbase[n >> 8];
}

// ---------------------------------------------------------------------------
// Kernel 1: normalize indices to int32 + degree histogram + x->fp16 convert
// (merged: the two tasks are independent; 800K threads cover both).
// Dtype self-detect per block (int64 => first 64 odd 32-bit words all zero).
// ---------------------------------------------------------------------------
__global__ __launch_bounds__(256) void convert_kernel(const void* __restrict__ ei,
                                                      const float* __restrict__ x) {
    const int* ei32 = (const int*)ei;
    __shared__ int s_is64;
    if (threadIdx.x == 0) s_is64 = 1;
    __syncthreads();
    if (threadIdx.x < 64 && ei32[2 * threadIdx.x + 1] != 0) atomicExch(&s_is64, 0);
    __syncthreads();

    int e = blockIdx.x * blockDim.x + threadIdx.x;
    if (e < EE) {
        int s, d;
        if (s_is64) {
            const long long* p = (const long long*)ei;
            s = (int)p[e];
            d = (int)p[EE + e];
        } else {
            const int* p = (const int*)ei;
            s = p[e];
            d = p[EE + e];
        }
        s = min(max(s, 0), NN - 1);
        d = min(max(d, 0), NN - 1);
        g_src32[e] = s;
        g_dst32[e] = d;
        atomicAdd(&g_deg[d], 1);
    }

    // x -> fp16 (grid-stride; 1.6M elements over 800K threads = 2 each)
    int stride = gridDim.x * 256;
    for (int i = blockIdx.x * 256 + threadIdx.x; i < NN * DD / 2; i += stride) {
        float2 v = reinterpret_cast<const float2*>(x)[i];
        g_xh[i] = __floats2half2_rn(v.x, v.y);
    }
}

// ---------------------------------------------------------------------------
// Kernel 2: single-pass exclusive scan (decoupled last-block)
// ---------------------------------------------------------------------------
__global__ __launch_bounds__(256) void scan_kernel() {
    __shared__ int sh[256];
    __shared__ int is_last;
    int tid = threadIdx.x;
    int i = blockIdx.x * 256 + tid;
    int v = (i < NN) ? g_deg[i] : 0;
    sh[tid] = v;
    __syncthreads();
    #pragma unroll
    for (int d = 1; d < 256; d <<= 1) {
        int t = (tid >= d) ? sh[tid - d] : 0;
        __syncthreads();
        sh[tid] += t;
        __syncthreads();
    }
    if (i < NN) g_loc[i] = sh[tid] - v;
    if (tid == 255) g_bsum[blockIdx.x] = sh[255];

    __threadfence();
    if (tid == 0) is_last = (atomicAdd(&g_scan_count, 1) == NB - 1);
    __syncthreads();

    if (is_last) {
        int v2 = (tid < NB) ? g_bsum[tid] : 0;
        sh[tid] = v2;
        __syncthreads();
        #pragma unroll
        for (int d = 1; d < 256; d <<= 1) {
            int t = (tid >= d) ? sh[tid - d] : 0;
            __syncthreads();
            sh[tid] += t;
            __syncthreads();
        }
        if (tid < NB) g_bbase[tid] = sh[tid] - v2;
        if (tid == 0) g_scan_count = 0;
    }
}

// ---------------------------------------------------------------------------
// Kernel 3: CSR fill (1 edge/thread). g_deg drains to 0.
// ---------------------------------------------------------------------------
__global__ __launch_bounds__(256) void fill_kernel() {
    int e = blockIdx.x * blockDim.x + threadIdx.x;
    if (e >= EE) return;
    int d = g_dst32[e];
    int off = node_off(d);
    int slot = atomicSub(&g_deg[d], 1) - 1;
    g_csr_src[off + slot] = g_src32[e];
}

// ---------------------------------------------------------------------------
// ldmatrix / mma helpers
// ---------------------------------------------------------------------------
__device__ __forceinline__ void ldsm_x4(uint32_t addr, uint32_t& a0, uint32_t& a1,
                                        uint32_t& a2, uint32_t& a3) {
    asm volatile("ldmatrix.sync.aligned.m8n8.x4.shared.b16 {%0,%1,%2,%3}, [%4];"
                 : "=r"(a0), "=r"(a1), "=r"(a2), "=r"(a3) : "r"(addr));
}
__device__ __forceinline__ void ldsm_x2(uint32_t addr, uint32_t& b0, uint32_t& b1) {
    asm volatile("ldmatrix.sync.aligned.m8n8.x2.shared.b16 {%0,%1}, [%2];"
                 : "=r"(b0), "=r"(b1) : "r"(addr));
}
__device__ __forceinline__ void mma16816(float* c, uint32_t a0, uint32_t a1,
                                         uint32_t a2, uint32_t a3,
                                         uint32_t b0, uint32_t b1) {
    asm volatile(
        "mma.sync.aligned.m16n8k16.row.col.f32.f16.f16.f32 "
        "{%0,%1,%2,%3}, {%4,%5,%6,%7}, {%8,%9}, {%0,%1,%2,%3};"
        : "+f"(c[0]), "+f"(c[1]), "+f"(c[2]), "+f"(c[3])
        : "r"(a0), "r"(a1), "r"(a2), "r"(a3), "r"(b0), "r"(b1));
}

#define ACCH(a, u) {                                            \
    __half2 _h0 = *reinterpret_cast<const __half2*>(&(u).x);    \
    __half2 _h1 = *reinterpret_cast<const __half2*>(&(u).y);    \
    float2 _f0 = __half22float2(_h0);                           \
    float2 _f1 = __half22float2(_h1);                           \
    (a).x += _f0.x; (a).y += _f0.y; (a).z += _f1.x; (a).w += _f1.y; }

// ---------------------------------------------------------------------------
// Kernel 4/5: FUSED aggregation + tensor-core MLP (R14 win, byte-identical).
// One 64-node group per block, 256 threads, static smem ~35KB.
// ---------------------------------------------------------------------------
template <int LAYER>
__global__ __launch_bounds__(256) void fused_kernel(
    const float* __restrict__ Wl,
    const float* __restrict__ bl,
    const float* __restrict__ Wr,
    float* __restrict__ outext)
{
    const __half2* nb = (LAYER == 1) ? g_xh : g_hh;   // fp16 rows (neighbors+self)

    __shared__ __half sI[64 * PH];
    __shared__ __half sW[64 * PH];
    __shared__ float  sB[DD];

    // Stage combined weights [j][k0..127] as fp16
    for (int t = threadIdx.x; t < 64 * 128; t += 256) {
        int j = t >> 7, kk = t & 127;
        float v = (kk < 64) ? Wl[(j << 6) + kk] : Wr[(j << 6) + kk - 64];
        sW[j * PH + kk] = __float2half_rn(v);
    }
    if (threadIdx.x < DD) sB[threadIdx.x] = bl[threadIdx.x];

    const int wid  = threadIdx.x >> 5;
    const int lane = threadIdx.x & 31;
    const int half = lane >> 4;
    const int fl   = lane & 15;
    const int fo   = fl << 2;

    const int base = blockIdx.x << 6;

    // ---- Gather + stage: half-warp owns 4 nodes, processed as 2 pairs ----
    #pragma unroll 1
    for (int pp = 0; pp < 2; pp++) {
        int nodeA = (wid << 3) + (pp << 2) + half;
        int nodeB = nodeA + 2;
        int niA = base + nodeA;
        int niB = base + nodeB;
        int begA = 0, lenA = 0, begB = 0, lenB = 0;
        if (niA < NN) {
            begA = node_off(niA);
            lenA = ((niA + 1 < NN) ? node_off(niA + 1) : EE) - begA;
        }
        if (niB < NN) {
            begB = node_off(niB);
            lenB = ((niB + 1 < NN) ? node_off(niB + 1) : EE) - begB;
        }

        float4 aA0 = make_float4(0.f, 0.f, 0.f, 0.f);
        float4 aA1 = make_float4(0.f, 0.f, 0.f, 0.f);
        float4 aB0 = make_float4(0.f, 0.f, 0.f, 0.f);
        float4 aB1 = make_float4(0.f, 0.f, 0.f, 0.f);

        int m = max(lenA, lenB);
        #pragma unroll 1
        for (int i = 0; i < m; i += 2) {
            int sA0 = (i     < lenA) ? g_csr_src[begA + i]     : -1;
            int sA1 = (i + 1 < lenA) ? g_csr_src[begA + i + 1] : -1;
            int sB0 = (i     < lenB) ? g_csr_src[begB + i]     : -1;
            int sB1 = (i + 1 < lenB) ? g_csr_src[begB + i + 1] : -1;
            if (sA0 >= 0) { uint2 u = reinterpret_cast<const uint2*>(nb + (size_t)sA0 * 32)[fl]; ACCH(aA0, u); }
            if (sA1 >= 0) { uint2 u = reinterpret_cast<const uint2*>(nb + (size_t)sA1 * 32)[fl]; ACCH(aA1, u); }
            if (sB0 >= 0) { uint2 u = reinterpret_cast<const uint2*>(nb + (size_t)sB0 * 32)[fl]; ACCH(aB0, u); }
            if (sB1 >= 0) { uint2 u = reinterpret_cast<const uint2*>(nb + (size_t)sB1 * 32)[fl]; ACCH(aB1, u); }
        }

        float invA = 1.0f / (float)max(lenA, 1);
        float invB = 1.0f / (float)max(lenB, 1);
        {
            __half2 p0 = __floats2half2_rn((aA0.x + aA1.x) * invA, (aA0.y + aA1.y) * invA);
            __half2 p1 = __floats2half2_rn((aA0.z + aA1.z) * invA, (aA0.w + aA1.w) * invA);
            uint2 u; u.x = *reinterpret_cast<uint32_t*>(&p0); u.y = *reinterpret_cast<uint32_t*>(&p1);
            *reinterpret_cast<uint2*>(&sI[nodeA * PH + fo]) = u;
        }
        {
            __half2 p0 = __floats2half2_rn((aB0.x + aB1.x) * invB, (aB0.y + aB1.y) * invB);
            __half2 p1 = __floats2half2_rn((aB0.z + aB1.z) * invB, (aB0.w + aB1.w) * invB);
            uint2 u; u.x = *reinterpret_cast<uint32_t*>(&p0); u.y = *reinterpret_cast<uint32_t*>(&p1);
            *reinterpret_cast<uint2*>(&sI[nodeB * PH + fo]) = u;
        }

        uint2 uA = make_uint2(0u, 0u), uB = make_uint2(0u, 0u);
        if (niA < NN) uA = reinterpret_cast<const uint2*>(nb + (size_t)niA * 32)[fl];
        if (niB < NN) uB = reinterpret_cast<const uint2*>(nb + (size_t)niB * 32)[fl];
        *reinterpret_cast<uint2*>(&sI[nodeA * PH + DD + fo]) = uA;
        *reinterpret_cast<uint2*>(&sI[nodeB * PH + DD + fo]) = uB;
    }
    __syncthreads();

    // ---- Compute: tensor cores. Warp tile: 16 nodes x 32 j ----
    const int mw = (wid & 3) << 4;
    const int jw = (wid >> 2) << 5;

    float c[4][4];
    #pragma unroll
    for (int js = 0; js < 4; js++)
        #pragma unroll
        for (int q = 0; q < 4; q++) c[js][q] = 0.f;

    uint32_t siBase = (uint32_t)__cvta_generic_to_shared(sI);
    uint32_t swBase = (uint32_t)__cvta_generic_to_shared(sW);
    const int rA = lane & 15, cbA = lane >> 4;
    const int rB = lane & 7,  kbB = (lane >> 3) & 1;

    #pragma unroll
    for (int ks = 0; ks < 8; ks++) {
        int k0 = ks << 4;
        uint32_t a0, a1, a2, a3;
        ldsm_x4(siBase + (uint32_t)(((mw + rA) * PH + k0 + cbA * 8) * 2), a0, a1, a2, a3);
        #pragma unroll
        for (int js = 0; js < 4; js++) {
            uint32_t b0, b1;
            ldsm_x2(swBase + (uint32_t)(((jw + (js << 3) + rB) * PH + k0 + kbB * 8) * 2), b0, b1);
            mma16816(c[js], a0, a1, a2, a3, b0, b1);
        }
    }

    // ---- Epilogue ----
    const int r1 = mw + (lane >> 2);
    const int r2 = r1 + 8;
    const int cc = (lane & 3) << 1;
    const int ni1 = base + r1;
    const int ni2 = base + r2;

    #pragma unroll
    for (int js = 0; js < 4; js++) {
        int j = jw + (js << 3) + cc;
        float bx = sB[j], by = sB[j + 1];
        float v0 = c[js][0] + bx, v1 = c[js][1] + by;
        float v2 = c[js][2] + bx, v3 = c[js][3] + by;
        if (LAYER == 1) {
            v0 = tanhf(v0); v1 = tanhf(v1);
            v2 = tanhf(v2); v3 = tanhf(v3);
            if (ni1 < NN) g_hh[(size_t)ni1 * 32 + (j >> 1)] = __floats2half2_rn(v0, v1);
            if (ni2 < NN) g_hh[(size_t)ni2 * 32 + (j >> 1)] = __floats2half2_rn(v2, v3);
        } else {
            if (ni1 < NN) *reinterpret_cast<float2*>(outext + (size_t)ni1 * DD + j) = make_float2(v0, v1);
            if (ni2 < NN) *reinterpret_cast<float2*>(outext + (size_t)ni2 * DD + j) = make_float2(v2, v3);
        }
    }
}

// ---------------------------------------------------------------------------
// Launch
// ---------------------------------------------------------------------------
extern "C" void kernel_launch(void* const* d_in, const int* in_sizes, int n_in,
                              void* d_out, int out_size)
{
    const float* x    = (const float*)d_in[0];
    const void*  ei   = d_in[1];
    const float* Wl1  = (const float*)d_in[2];
    const float* bl1  = (const float*)d_in[3];
    const float* Wr1  = (const float*)d_in[4];
    const float* Wl2  = (const float*)d_in[5];
    const float* bl2  = (const float*)d_in[6];
    const float* Wr2  = (const float*)d_in[7];
    float*       out  = (float*)d_out;

    static void* deg_addr = nullptr;
    if (!deg_addr) cudaGetSymbolAddress(&deg_addr, g_deg);

    const int eb = (EE + 255) / 256;        // 1 edge/thread blocks
    const int fb = (NN + 63) / 64;          // 782 fused blocks

    cudaMemsetAsync(deg_addr, 0, NN * sizeof(int));
    convert_kernel<<<eb, 256>>>(ei, x);
    scan_kernel<<<NB, 256>>>();
    fill_kernel<<<eb, 256>>>();
    fused_kernel<1><<<fb, 256>>>(Wl1, bl1, Wr1, nullptr);
    fused_kernel<2><<<fb, 256>>>(Wl2, bl2, Wr2, out);
}